// round 12
// baseline (speedup 1.0000x reference)
#include <cuda_runtime.h>

#define NV 50000
#define GD 10
#define GH 162
#define GW 162
#define NPART 240

// ---------------- device scratch (no allocations allowed) ----------------
__device__ int    g_grid[2 * GD * GH * GW];              // padded hash grid
__device__ int    g_nbr[27 * NV];                        // rulebook [k][n]
__device__ float4 g_phi[(NV + 1) * 64];                  // expanded features; pad row = phi(0)
__device__ __align__(16) float g_wc[27 * 256 * 128];     // combined weights [k][4Cin][Cout]
__device__ __align__(16) float g_raw[NV * 128];          // pre-BN conv output
__device__ float  g_part[NPART * 2 * 128];               // BN partial sums
__device__ float  g_mu[128];
__device__ float  g_istd[128];

// ---------------- small utility kernels ----------------
__global__ void k_zero4(float4* p, long n4) {
    long i = (long)blockIdx.x * blockDim.x + threadIdx.x;
    if (i < n4) p[i] = make_float4(0.f, 0.f, 0.f, 0.f);
}

__global__ void k_initgrid() {
    int i = blockIdx.x * blockDim.x + threadIdx.x;
    if (i < 2 * GD * GH * GW) g_grid[i] = NV;   // sentinel = NV (pad row)
}

__global__ void k_scatgrid(const int* __restrict__ coors) {
    int n = blockIdx.x * blockDim.x + threadIdx.x;
    if (n >= NV) return;
    int b = coors[4 * n], z = coors[4 * n + 1], y = coors[4 * n + 2], x = coors[4 * n + 3];
    g_grid[((b * GD + z + 1) * GH + y + 1) * GW + x + 1] = n;
}

__global__ void k_nbr(const int* __restrict__ coors) {
    int n = blockIdx.x * blockDim.x + threadIdx.x;
    if (n >= NV) return;
    int b = coors[4 * n], z = coors[4 * n + 1] + 1, y = coors[4 * n + 2] + 1, x = coors[4 * n + 3] + 1;
    int k = 0;
#pragma unroll
    for (int dz = -1; dz <= 1; dz++)
#pragma unroll
        for (int dy = -1; dy <= 1; dy++)
#pragma unroll
            for (int dx = -1; dx <= 1; dx++) {
                g_nbr[k * NV + n] = g_grid[((b * GD + z + dz) * GH + y + dy) * GW + x + dx];
                k++;
            }
}

// phi(x) = (silu(x), exp(-(x+1)^2), exp(-x^2), exp(-(x-1)^2))   [centers -1,0,1, inv_h=1]
__device__ __forceinline__ float4 phi_of(float x) {
    float s  = x / (1.f + expf(-x));
    float b0 = expf(-(x + 1.f) * (x + 1.f));
    float b1 = expf(-x * x);
    float b2 = expf(-(x - 1.f) * (x - 1.f));
    return make_float4(s, b0, b1, b2);
}

// layer-1 phi from external voxel features; pad row n==NV gets phi(0)
__global__ void k_phi_in(const float* __restrict__ ext) {
    int t = blockIdx.x * blockDim.x + threadIdx.x;
    if (t >= (NV + 1) * 16) return;
    float x = (t < NV * 16) ? ext[t] : 0.f;
    g_phi[t] = phi_of(x);
}

// fused BN(train stats) + ReLU + phi expansion for intermediate layers
template <int COUT>
__global__ void k_bnphi(const float* __restrict__ gm, const float* __restrict__ bt) {
    long t = (long)blockIdx.x * 256 + threadIdx.x;
    if (t >= (long)(NV + 1) * COUT) return;
    float x = 0.f;
    if (t < (long)NV * COUT) {
        int col = (int)(t % COUT);
        float v = (g_raw[t] - g_mu[col]) * g_istd[col] * gm[col] + bt[col];
        x = fmaxf(v, 0.f);
    }
    g_phi[t] = phi_of(x);
}

// fused BN + ReLU + dense scatter for the final layer: out[b, c*8+z, y, x]
__global__ void k_bnscat(const int* __restrict__ coors,
                         const float* __restrict__ gm, const float* __restrict__ bt,
                         float* __restrict__ out) {
    long t = (long)blockIdx.x * 256 + threadIdx.x;
    if (t >= (long)NV * 128) return;
    int n = (int)(t >> 7);
    int c = (int)(t & 127);
    float v = (g_raw[t] - g_mu[c]) * g_istd[c] * gm[c] + bt[c];
    v = fmaxf(v, 0.f);
    int b = coors[4 * n], z = coors[4 * n + 1], y = coors[4 * n + 2], x = coors[4 * n + 3];
    long oi = (((long)(b * 1024 + c * 8 + z)) * 160 + y) * 160 + x;
    out[oi] = v;
}

// Combined weight: Wc[k][c*4+0][o]=wb[k,c,o];  Wc[k][c*4+1+g][o]=ws[k,c,g,o]
template <int CIN, int COUT>
__global__ void k_wc(const float* __restrict__ wb, const float* __restrict__ ws) {
    int t = blockIdx.x * blockDim.x + threadIdx.x;
    if (t >= 27 * 4 * CIN * COUT) return;
    int o = t % COUT;
    int r = t / COUT;
    int j = r % (4 * CIN);
    int k = r / (4 * CIN);
    int c = j >> 2, jj = j & 3;
    g_wc[t] = (jj == 0) ? wb[(k * CIN + c) * COUT + o]
                        : ws[((k * CIN + c) * 3 + (jj - 1)) * COUT + o];
}

// ---------------- gather-GEMM with packed f32x2 FMA, fat thread tiles ----------------
__device__ __forceinline__ unsigned long long ffma2(unsigned long long a,
                                                    unsigned long long b,
                                                    unsigned long long c) {
    unsigned long long d;
    asm("fma.rn.f32x2 %0, %1, %2, %3;" : "=l"(d) : "l"(a), "l"(b), "l"(c));
    return d;
}

// out[m, nofs+o] = sum_k sum_j phi[nbr[k][m]][j] * Wc[k][j][nofs+o]
// CTA = TM=256 voxels x COUT_T cols, 256 threads. Thread tile: RT voxels
// (RT/2 f32x2 M-pairs) x TN cols. Fat tiles (RT=16 on big layers) give
// 32 FFMA2 per ~16 non-FMA insts per j -> issue slack absorbs LDS latency.
// LDGs for the chunk are issued BEFORE the chunk barrier so their latency
// hides behind the barrier wait; registers are not live across compute.
template <int CIN, int COUT, int COUT_T, int RT, int TN>
__global__ __launch_bounds__(256) void k_gemm() {
    constexpr int KD  = 4 * CIN;           // reduction length per tap
    constexpr int KC  = 32;                // k-chunk
    constexpr int CPT = KD / KC;           // chunks per tap
    constexpr int NCH = 27 * CPT;
    constexpr int TM  = 256;
    constexpr int TNG = COUT_T / TN;       // thread groups along N
    constexpr int P   = RT / 2;            // f32x2 M-pairs per thread
    constexpr int WF2 = KC * COUT_T / 512; // float2s of W per thread
    static_assert((256 / TNG) * RT == TM, "tiling");
    static_assert((KC * COUT_T) % 512 == 0 && P % 2 == 0 && WF2 >= 1, "vec");

    __shared__ __align__(16) float As[KC][TM];
    __shared__ __align__(16) float Ws[KC][COUT_T];

    int tid  = threadIdx.x;
    int tx   = tid % TNG;
    int ty   = tid / TNG;
    int row0 = ty * RT;
    int m0   = blockIdx.x * TM;
    int nofs = blockIdx.y * COUT_T;
    int am   = m0 + tid;                   // TPR=1: this thread's gather row
    bool avalid = (am < NV);

    unsigned long long acc[P][TN];
#pragma unroll
    for (int p = 0; p < P; p++)
#pragma unroll
        for (int i = 0; i < TN; i++) acc[p][i] = 0ull;

    int idx = NV;
    for (int cid = 0; cid < NCH; cid++) {
        int tap = cid / CPT;
        int jc  = (cid % CPT) * KC;

        // issue chunk LDGs before the barrier (latency hides behind barrier wait)
        if (cid % CPT == 0)
            idx = avalid ? __ldg(&g_nbr[tap * NV + am]) : NV;   // NV -> phi(0) pad row
        float4 areg[8];                                          // KC floats = 8 float4
        const float4* prow = g_phi + (size_t)idx * CIN + (jc >> 2);
#pragma unroll
        for (int q = 0; q < 8; q++) areg[q] = prow[q];
        float2 wreg[WF2];
        const float* wbase = g_wc + ((size_t)tap * KD + jc) * COUT + nofs;
#pragma unroll
        for (int v = 0; v < WF2; v++) {
            int e = (tid + v * 256) * 2;
            wreg[v] = *(const float2*)(wbase + (size_t)(e / COUT_T) * COUT + (e % COUT_T));
        }

        __syncthreads();   // previous compute done reading SMEM
#pragma unroll
        for (int q = 0; q < 8; q++) {
            float4 v = areg[q];
            As[4 * q + 0][tid] = v.x;
            As[4 * q + 1][tid] = v.y;
            As[4 * q + 2][tid] = v.z;
            As[4 * q + 3][tid] = v.w;
        }
#pragma unroll
        for (int v = 0; v < WF2; v++) ((float2*)Ws)[tid + v * 256] = wreg[v];
        __syncthreads();

#pragma unroll
        for (int j = 0; j < KC; j++) {
            unsigned long long a[P];
            const ulonglong2* ap = (const ulonglong2*)&As[j][row0];
#pragma unroll
            for (int h = 0; h < P / 2; h++) {        // warp-broadcast LDS.128
                ulonglong2 t2 = ap[h];
                a[2 * h]     = t2.x;
                a[2 * h + 1] = t2.y;
            }
#pragma unroll
            for (int i = 0; i < TN; i++) {
                unsigned int bi = __float_as_uint(Ws[j][tx + i * TNG]);
                unsigned long long b2;
                asm("mov.b64 %0, {%1, %1};" : "=l"(b2) : "r"(bi));
#pragma unroll
                for (int p = 0; p < P; p++)
                    acc[p][i] = ffma2(a[p], b2, acc[p][i]);
            }
        }
    }

    // epilogue: unpack f32x2 pairs, store pre-BN output
#pragma unroll
    for (int p = 0; p < P; p++) {
        int r = m0 + row0 + 2 * p;
#pragma unroll
        for (int i = 0; i < TN; i++) {
            unsigned int lo, hi;
            asm("mov.b64 {%0, %1}, %2;" : "=r"(lo), "=r"(hi) : "l"(acc[p][i]));
            int col = nofs + tx + i * TNG;
            if (r < NV)     g_raw[(size_t)r * COUT + col]       = __uint_as_float(lo);
            if (r + 1 < NV) g_raw[(size_t)(r + 1) * COUT + col] = __uint_as_float(hi);
        }
    }
}

// ---------------- BatchNorm statistics (deterministic tree reduction) ----------------
template <int COUT>
__global__ void k_stats1() {
    constexpr int RP = 256 / COUT;
    int tid = threadIdx.x;
    int col = tid % COUT, rg = tid / COUT;
    float s = 0.f, q = 0.f;
    for (int r = blockIdx.x * RP + rg; r < NV; r += NPART * RP) {
        float v = g_raw[(size_t)r * COUT + col];
        s += v;
        q += v * v;
    }
    __shared__ float sh[256], sh2[256];
    sh[tid] = s; sh2[tid] = q;
    __syncthreads();
    if (rg == 0) {
#pragma unroll
        for (int g2 = 1; g2 < RP; g2++) { s += sh[g2 * COUT + col]; q += sh2[g2 * COUT + col]; }
        g_part[blockIdx.x * 2 * COUT + col]        = s;
        g_part[blockIdx.x * 2 * COUT + COUT + col] = q;
    }
}

template <int COUT>
__global__ void k_stats2() {
    int col = threadIdx.x;
    if (col >= COUT) return;
    double s = 0.0, q = 0.0;
    for (int b = 0; b < NPART; b++) {
        s += (double)g_part[b * 2 * COUT + col];
        q += (double)g_part[b * 2 * COUT + COUT + col];
    }
    double mu  = s / (double)NV;
    double var = q / (double)NV - mu * mu;
    g_mu[col]   = (float)mu;
    g_istd[col] = (float)(1.0 / sqrt(var + 1e-3));
}

// ---------------- host orchestration ----------------
template <int CIN, int COUT, int COUT_T, int RT, int TN>
static void run_gemm_block(const float* wb, const float* ws) {
    k_wc<CIN, COUT><<<(27 * 4 * CIN * COUT + 255) / 256, 256>>>(wb, ws);
    dim3 grid((NV + 255) / 256, COUT / COUT_T);
    k_gemm<CIN, COUT, COUT_T, RT, TN><<<grid, 256>>>();
    k_stats1<COUT><<<NPART, 256>>>();
    k_stats2<COUT><<<1, 128>>>();
}

extern "C" void kernel_launch(void* const* d_in, const int* in_sizes, int n_in,
                              void* d_out, int out_size) {
    const float* vf    = (const float*)d_in[0];
    const int*   coors = (const int*)d_in[1];
    // d_in[2] = batch_size (compile-time B=2)
    const float *wb[5], *ws[5], *gm[5], *bt[5];
    for (int i = 0; i < 5; i++) {
        wb[i] = (const float*)d_in[3 + 4 * i];
        ws[i] = (const float*)d_in[4 + 4 * i];
        gm[i] = (const float*)d_in[5 + 4 * i];
        bt[i] = (const float*)d_in[6 + 4 * i];
    }

    // rulebook + layer-1 phi
    k_initgrid<<<(2 * GD * GH * GW + 255) / 256, 256>>>();
    k_scatgrid<<<(NV + 255) / 256, 256>>>(coors);
    k_nbr<<<(NV + 255) / 256, 256>>>(coors);
    k_phi_in<<<(((NV + 1) * 16) + 255) / 256, 256>>>(vf);

    // L1: 16 -> 16   (RT=8, TN=2: acc 8 regs)
    run_gemm_block<16, 16, 16, 8, 2>(wb[0], ws[0]);
    k_bnphi<16><<<(int)((((long)(NV + 1) * 16) + 255) / 256), 256>>>(gm[0], bt[0]);

    // L2: 16 -> 32   (RT=8, TN=4: acc 16 regs)
    run_gemm_block<16, 32, 32, 8, 4>(wb[1], ws[1]);
    k_bnphi<32><<<(int)((((long)(NV + 1) * 32) + 255) / 256), 256>>>(gm[1], bt[1]);

    // L3: 32 -> 64   (RT=16, TN=4: 32 FFMA2 per j, acc 64 regs)
    run_gemm_block<32, 64, 64, 16, 4>(wb[2], ws[2]);
    k_bnphi<64><<<(int)((((long)(NV + 1) * 64) + 255) / 256), 256>>>(gm[2], bt[2]);

    // L4: 64 -> 64
    run_gemm_block<64, 64, 64, 16, 4>(wb[3], ws[3]);
    k_bnphi<64><<<(int)((((long)(NV + 1) * 64) + 255) / 256), 256>>>(gm[3], bt[3]);

    // L5: 64 -> 128, N-split into two 64-col halves
    run_gemm_block<64, 128, 64, 16, 4>(wb[4], ws[4]);

    // zero dense output (poisoned by harness), then fused BN+ReLU+scatter
    long n4 = (long)out_size / 4;
    k_zero4<<<(int)((n4 + 255) / 256), 256>>>((float4*)d_out, n4);
    k_bnscat<<<(int)((((long)NV * 128) + 255) / 256), 256>>>(coors, gm[4], bt[4], (float*)d_out);
}

// round 15
// speedup vs baseline: 1.7992x; 1.7992x over previous
#include <cuda_runtime.h>
#include <cuda_bf16.h>

#define NV 50000
#define GD 10
#define GH 162
#define GW 162
#define NPART 240

// ---------------- device scratch (no allocations allowed) ----------------
__device__ int    g_grid[2 * GD * GH * GW];
__device__ int    g_nbr[27 * NV];
__device__ float4 g_phi[(NV + 1) * 16];                                 // f32 phi (CIN=16 layers)
__device__ __align__(16) unsigned short g_phh[(size_t)(NV + 1) * 256];  // bf16 hi phi
__device__ __align__(16) unsigned short g_phl[(size_t)(NV + 1) * 256];  // bf16 lo phi
__device__ __align__(16) unsigned short g_w3h[27 * 8 * 2 * 2560];       // W^T hi tiles [o][k] pad40
__device__ __align__(16) unsigned short g_w3l[27 * 8 * 2 * 2560];       // W^T lo tiles
__device__ __align__(16) float g_wc[27 * 64 * 32];                      // f32 W (L1/L2)
__device__ __align__(16) float g_raw[NV * 128];
__device__ float g_part[NPART * 2 * 128];
__device__ float g_mu[128];
__device__ float g_istd[128];

// ---------------- helpers ----------------
__device__ __forceinline__ unsigned smem_u32(const void* p) {
    unsigned a;
    asm("{ .reg .u64 t; cvta.to.shared.u64 t, %1; cvt.u32.u64 %0, t; }" : "=r"(a) : "l"(p));
    return a;
}
#define LDSM4(rg, addr)                                                              \
    asm volatile("ldmatrix.sync.aligned.m8n8.x4.shared.b16 {%0,%1,%2,%3}, [%4];"     \
        : "=r"((rg)[0]), "=r"((rg)[1]), "=r"((rg)[2]), "=r"((rg)[3]) : "r"(addr))
#define MMA_BF16(d, a, b0, b1)                                                       \
    asm volatile("mma.sync.aligned.m16n8k16.row.col.f32.bf16.bf16.f32 "              \
        "{%0,%1,%2,%3}, {%4,%5,%6,%7}, {%8,%9}, {%0,%1,%2,%3};"                      \
        : "+f"((d)[0]), "+f"((d)[1]), "+f"((d)[2]), "+f"((d)[3])                     \
        : "r"((a)[0]), "r"((a)[1]), "r"((a)[2]), "r"((a)[3]), "r"(b0), "r"(b1))

// ---------------- small utility kernels ----------------
__global__ void k_zero4(float4* p, long n4) {
    long i = (long)blockIdx.x * blockDim.x + threadIdx.x;
    if (i < n4) p[i] = make_float4(0.f, 0.f, 0.f, 0.f);
}

__global__ void k_initgrid() {
    int i = blockIdx.x * blockDim.x + threadIdx.x;
    if (i < 2 * GD * GH * GW) g_grid[i] = NV;
}

__global__ void k_scatgrid(const int* __restrict__ coors) {
    int n = blockIdx.x * blockDim.x + threadIdx.x;
    if (n >= NV) return;
    int b = coors[4 * n], z = coors[4 * n + 1], y = coors[4 * n + 2], x = coors[4 * n + 3];
    g_grid[((b * GD + z + 1) * GH + y + 1) * GW + x + 1] = n;
}

__global__ void k_nbr(const int* __restrict__ coors) {
    int n = blockIdx.x * blockDim.x + threadIdx.x;
    if (n >= NV) return;
    int b = coors[4 * n], z = coors[4 * n + 1] + 1, y = coors[4 * n + 2] + 1, x = coors[4 * n + 3] + 1;
    int k = 0;
#pragma unroll
    for (int dz = -1; dz <= 1; dz++)
#pragma unroll
        for (int dy = -1; dy <= 1; dy++)
#pragma unroll
            for (int dx = -1; dx <= 1; dx++) {
                g_nbr[k * NV + n] = g_grid[((b * GD + z + dz) * GH + y + dy) * GW + x + dx];
                k++;
            }
}

__device__ __forceinline__ float4 phi_of(float x) {
    float s  = x / (1.f + expf(-x));
    float b0 = expf(-(x + 1.f) * (x + 1.f));
    float b1 = expf(-x * x);
    float b2 = expf(-(x - 1.f) * (x - 1.f));
    return make_float4(s, b0, b1, b2);
}

__global__ void k_phi_in(const float* __restrict__ ext) {
    int t = blockIdx.x * blockDim.x + threadIdx.x;
    if (t >= (NV + 1) * 16) return;
    float x = (t < NV * 16) ? ext[t] : 0.f;
    g_phi[t] = phi_of(x);
}

// BN + ReLU + f32 phi (feeds L2's f32x2 GEMM)
template <int COUT>
__global__ void k_bnphi(const float* __restrict__ gm, const float* __restrict__ bt) {
    long t = (long)blockIdx.x * 256 + threadIdx.x;
    if (t >= (long)(NV + 1) * COUT) return;
    float x = 0.f;
    if (t < (long)NV * COUT) {
        int col = (int)(t % COUT);
        float v = (g_raw[t] - g_mu[col]) * g_istd[col] * gm[col] + bt[col];
        x = fmaxf(v, 0.f);
    }
    g_phi[t] = phi_of(x);
}

// BN + ReLU + bf16 hi/lo phi split (feeds tensor layers)
template <int COUT>
__global__ void k_bnphib(const float* __restrict__ gm, const float* __restrict__ bt) {
    long t = (long)blockIdx.x * 256 + threadIdx.x;
    if (t >= (long)(NV + 1) * COUT) return;
    float x = 0.f;
    if (t < (long)NV * COUT) {
        int col = (int)(t % COUT);
        float v = (g_raw[t] - g_mu[col]) * g_istd[col] * gm[col] + bt[col];
        x = fmaxf(v, 0.f);
    }
    float4 p = phi_of(x);
    float vals[4] = {p.x, p.y, p.z, p.w};
    size_t b = (size_t)t * 4;
#pragma unroll
    for (int i = 0; i < 4; i++) {
        __nv_bfloat16 h = __float2bfloat16_rn(vals[i]);
        __nv_bfloat16 l = __float2bfloat16_rn(vals[i] - __bfloat162float(h));
        g_phh[b + i] = __bfloat16_as_ushort(h);
        g_phl[b + i] = __bfloat16_as_ushort(l);
    }
}

__global__ void k_bnscat(const int* __restrict__ coors,
                         const float* __restrict__ gm, const float* __restrict__ bt,
                         float* __restrict__ out) {
    long t = (long)blockIdx.x * 256 + threadIdx.x;
    if (t >= (long)NV * 128) return;
    int n = (int)(t >> 7);
    int c = (int)(t & 127);
    float v = (g_raw[t] - g_mu[c]) * g_istd[c] * gm[c] + bt[c];
    v = fmaxf(v, 0.f);
    int b = coors[4 * n], z = coors[4 * n + 1], y = coors[4 * n + 2], x = coors[4 * n + 3];
    long oi = (((long)(b * 1024 + c * 8 + z)) * 160 + y) * 160 + x;
    out[oi] = v;
}

// combined f32 weights for L1/L2
template <int CIN, int COUT>
__global__ void k_wc(const float* __restrict__ wb, const float* __restrict__ ws) {
    int t = blockIdx.x * blockDim.x + threadIdx.x;
    if (t >= 27 * 4 * CIN * COUT) return;
    int o = t % COUT;
    int r = t / COUT;
    int j = r % (4 * CIN);
    int k = r / (4 * CIN);
    int c = j >> 2, jj = j & 3;
    g_wc[t] = (jj == 0) ? wb[(k * CIN + c) * COUT + o]
                        : ws[((k * CIN + c) * 3 + (jj - 1)) * COUT + o];
}

// W^T bf16 hi/lo tiles for tensor layers: tile(k, chunk, half) = [64 o-rows][32 k-cols pad 40]
template <int CIN, int COUT>
__global__ void k_wc3(const float* __restrict__ wb, const float* __restrict__ ws) {
    constexpr int KD = 4 * CIN, CPT = KD / 32, NH = COUT / 64;
    int t = blockIdx.x * blockDim.x + threadIdx.x;
    if (t >= 27 * KD * COUT) return;
    int o = t % COUT;
    int j = (t / COUT) % KD;
    int k = t / (COUT * KD);
    int c = j >> 2, jj = j & 3;
    float w = (jj == 0) ? wb[(k * CIN + c) * COUT + o]
                        : ws[((k * CIN + c) * 3 + (jj - 1)) * COUT + o];
    __nv_bfloat16 h = __float2bfloat16_rn(w);
    __nv_bfloat16 l = __float2bfloat16_rn(w - __bfloat162float(h));
    int tile = (k * CPT + (j >> 5)) * NH + (o >> 6);
    size_t dst = (size_t)tile * 2560 + (size_t)(o & 63) * 40 + (j & 31);
    g_w3h[dst] = __bfloat16_as_ushort(h);
    g_w3l[dst] = __bfloat16_as_ushort(l);
}

// ---------------- mma.sync bf16 gather-GEMM (L3/L4/L5) ----------------
// CTA: 128 voxels x 64 cols (half hy), 8 warps in 4(M) x 2(N); warp tile 32x32.
// Per 32-wide K chunk: gather Ahi+Alo, stage Whi+Wlo, then 3 MMA products
// (hi*hi + lo*hi + hi*lo) accumulate in f32 regs across 27 taps.
template <int CIN, int COUT>
__global__ __launch_bounds__(256) void k_hgemm() {
    constexpr int KD = 4 * CIN, CPT = KD / 32, NH = COUT / 64;
    __shared__ __align__(16) unsigned short Ah[128][40];
    __shared__ __align__(16) unsigned short Al[128][40];
    __shared__ __align__(16) unsigned short Wh[64][40];
    __shared__ __align__(16) unsigned short Wl[64][40];

    int tid  = threadIdx.x, lane = tid & 31, wid = tid >> 5;
    int wm   = wid & 3, wn = wid >> 2;
    int m0   = blockIdx.x * 128;
    int hy   = blockIdx.y;
    int nofs = hy * 64;
    int r    = tid >> 1, half = tid & 1;
    int am   = m0 + r;

    float acc[2][4][4];
#pragma unroll
    for (int mt = 0; mt < 2; mt++)
#pragma unroll
        for (int nf = 0; nf < 4; nf++)
#pragma unroll
            for (int e = 0; e < 4; e++) acc[mt][nf][e] = 0.f;

    // ldmatrix smem addresses (row parts; k-offset added per k-step)
    unsigned ah_base[2], al_base[2], bh_base[2], bl_base[2];
#pragma unroll
    for (int mt = 0; mt < 2; mt++) {
        int rowA = wm * 32 + mt * 16 + (lane & 15);
        unsigned co = (unsigned)(8 * (lane >> 4));
        ah_base[mt] = smem_u32(&Ah[rowA][0]) + co * 2;
        al_base[mt] = smem_u32(&Al[rowA][0]) + co * 2;
    }
#pragma unroll
    for (int nt = 0; nt < 2; nt++) {
        int rowB = wn * 32 + nt * 16 + (lane & 7) + ((lane >> 4) << 3);
        unsigned co = (unsigned)(((lane >> 3) & 1) * 8);
        bh_base[nt] = smem_u32(&Wh[rowB][0]) + co * 2;
        bl_base[nt] = smem_u32(&Wl[rowB][0]) + co * 2;
    }
    unsigned sAdst0 = smem_u32(&Ah[r][half * 16]);
    unsigned sAdst1 = smem_u32(&Al[r][half * 16]);

    for (int k = 0; k < 27; k++) {
        int idx = (am < NV) ? __ldg(&g_nbr[k * NV + am]) : NV;   // NV -> phi(0) pad row
        for (int q = 0; q < CPT; q++) {
            // issue chunk LDGs (overlap previous chunk's MMAs until first sync)
            const uint4* ph = (const uint4*)(g_phh + (size_t)idx * KD + q * 32 + half * 16);
            const uint4* pl = (const uint4*)(g_phl + (size_t)idx * KD + q * 32 + half * 16);
            uint4 h0 = ph[0], h1 = ph[1];
            uint4 l0 = pl[0], l1 = pl[1];
            int tile = (k * CPT + q) * NH + hy;
            const uint4* wph = (const uint4*)(g_w3h + (size_t)tile * 2560);
            const uint4* wpl = (const uint4*)(g_w3l + (size_t)tile * 2560);
            uint4 wh0 = wph[tid], wl0 = wpl[tid];               // 320 uint4 per image
            uint4 wh1, wl1;
            if (tid < 64) { wh1 = wph[tid + 256]; wl1 = wpl[tid + 256]; }

            __syncthreads();   // previous compute done with SMEM
            asm volatile("st.shared.v4.b32 [%0], {%1,%2,%3,%4};"
                         :: "r"(sAdst0), "r"(h0.x), "r"(h0.y), "r"(h0.z), "r"(h0.w) : "memory");
            asm volatile("st.shared.v4.b32 [%0], {%1,%2,%3,%4};"
                         :: "r"(sAdst0 + 16), "r"(h1.x), "r"(h1.y), "r"(h1.z), "r"(h1.w) : "memory");
            asm volatile("st.shared.v4.b32 [%0], {%1,%2,%3,%4};"
                         :: "r"(sAdst1), "r"(l0.x), "r"(l0.y), "r"(l0.z), "r"(l0.w) : "memory");
            asm volatile("st.shared.v4.b32 [%0], {%1,%2,%3,%4};"
                         :: "r"(sAdst1 + 16), "r"(l1.x), "r"(l1.y), "r"(l1.z), "r"(l1.w) : "memory");
            ((uint4*)Wh)[tid] = wh0;
            ((uint4*)Wl)[tid] = wl0;
            if (tid < 64) { ((uint4*)Wh)[tid + 256] = wh1; ((uint4*)Wl)[tid + 256] = wl1; }
            __syncthreads();

#pragma unroll
            for (int ks = 0; ks < 2; ks++) {
                unsigned ko = (unsigned)(ks * 32);   // 16 bf16 = 32 bytes
                unsigned ah[2][4], al[2][4], bh[2][4], bl[2][4];
#pragma unroll
                for (int mt = 0; mt < 2; mt++) {
                    LDSM4(ah[mt], ah_base[mt] + ko);
                    LDSM4(al[mt], al_base[mt] + ko);
                }
#pragma unroll
                for (int nt = 0; nt < 2; nt++) {
                    LDSM4(bh[nt], bh_base[nt] + ko);
                    LDSM4(bl[nt], bl_base[nt] + ko);
                }
#pragma unroll
                for (int mt = 0; mt < 2; mt++)
#pragma unroll
                    for (int nf = 0; nf < 4; nf++) {
                        unsigned bh0 = bh[nf >> 1][2 * (nf & 1)];
                        unsigned bh1 = bh[nf >> 1][2 * (nf & 1) + 1];
                        unsigned bl0 = bl[nf >> 1][2 * (nf & 1)];
                        unsigned bl1 = bl[nf >> 1][2 * (nf & 1) + 1];
                        MMA_BF16(acc[mt][nf], ah[mt], bh0, bh1);
                        MMA_BF16(acc[mt][nf], al[mt], bh0, bh1);
                        MMA_BF16(acc[mt][nf], ah[mt], bl0, bl1);
                    }
            }
        }
    }

    // epilogue: acc layout rows l/4 (+8), cols 2*(l%4) (+1)
#pragma unroll
    for (int mt = 0; mt < 2; mt++) {
#pragma unroll
        for (int nf = 0; nf < 4; nf++) {
            int rr = m0 + wm * 32 + mt * 16 + (lane >> 2);
            int cc = nofs + wn * 32 + nf * 8 + 2 * (lane & 3);
            if (rr < NV) {
                g_raw[(size_t)rr * COUT + cc]     = acc[mt][nf][0];
                g_raw[(size_t)rr * COUT + cc + 1] = acc[mt][nf][1];
            }
            if (rr + 8 < NV) {
                g_raw[(size_t)(rr + 8) * COUT + cc]     = acc[mt][nf][2];
                g_raw[(size_t)(rr + 8) * COUT + cc + 1] = acc[mt][nf][3];
            }
        }
    }
}

// ---------------- f32x2 gather-GEMM (L1/L2, proven) ----------------
__device__ __forceinline__ unsigned long long ffma2(unsigned long long a,
                                                    unsigned long long b,
                                                    unsigned long long c) {
    unsigned long long d;
    asm("fma.rn.f32x2 %0, %1, %2, %3;" : "=l"(d) : "l"(a), "l"(b), "l"(c));
    return d;
}

template <int CIN, int COUT, int RT, int TN>
__global__ __launch_bounds__(256) void k_gemm() {
    constexpr int KD  = 4 * CIN;
    constexpr int KC  = 32;
    constexpr int CPT = KD / KC;
    constexpr int NCH = 27 * CPT;
    constexpr int TM  = 256;
    constexpr int TNG = COUT / TN;
    constexpr int P   = RT / 2;
    constexpr int WF2 = KC * COUT / 512;
    static_assert((256 / TNG) * RT == TM && P % 2 == 0 && WF2 >= 1, "tiling");

    __shared__ __align__(16) float As[KC][TM];
    __shared__ __align__(16) float Ws[KC][COUT];

    int tid  = threadIdx.x;
    int tx   = tid % TNG;
    int ty   = tid / TNG;
    int row0 = ty * RT;
    int m0   = blockIdx.x * TM;
    int am   = m0 + tid;
    bool avalid = (am < NV);

    unsigned long long acc[P][TN];
#pragma unroll
    for (int p = 0; p < P; p++)
#pragma unroll
        for (int i = 0; i < TN; i++) acc[p][i] = 0ull;

    int idx = NV;
    for (int cid = 0; cid < NCH; cid++) {
        int tap = cid / CPT;
        int jc  = (cid % CPT) * KC;
        if (cid % CPT == 0)
            idx = avalid ? __ldg(&g_nbr[tap * NV + am]) : NV;
        float4 areg[8];
        const float4* prow = g_phi + (size_t)idx * CIN + (jc >> 2);
#pragma unroll
        for (int q = 0; q < 8; q++) areg[q] = prow[q];
        float2 wreg[WF2];
        const float2* wbase = (const float2*)(g_wc + ((size_t)tap * KD + jc) * COUT);
#pragma unroll
        for (int v = 0; v < WF2; v++) wreg[v] = wbase[tid + v * 256];

        __syncthreads();
#pragma unroll
        for (int q = 0; q < 8; q++) {
            float4 v = areg[q];
            As[4 * q + 0][tid] = v.x;
            As[4 * q + 1][tid] = v.y;
            As[4 * q + 2][tid] = v.z;
            As[4 * q + 3][tid] = v.w;
        }
#pragma unroll
        for (int v = 0; v < WF2; v++) ((float2*)Ws)[tid + v * 256] = wreg[v];
        __syncthreads();

#pragma unroll
        for (int j = 0; j < KC; j++) {
            unsigned long long a[P];
            const ulonglong2* ap = (const ulonglong2*)&As[j][row0];
#pragma unroll
            for (int h = 0; h < P / 2; h++) {
                ulonglong2 t2 = ap[h];
                a[2 * h]     = t2.x;
                a[2 * h + 1] = t2.y;
            }
#pragma unroll
            for (int i = 0; i < TN; i++) {
                unsigned int bi = __float_as_uint(Ws[j][tx + i * TNG]);
                unsigned long long b2;
                asm("mov.b64 %0, {%1, %1};" : "=l"(b2) : "r"(bi));
#pragma unroll
                for (int p = 0; p < P; p++)
                    acc[p][i] = ffma2(a[p], b2, acc[p][i]);
            }
        }
    }

#pragma unroll
    for (int p = 0; p < P; p++) {
        int r = m0 + row0 + 2 * p;
#pragma unroll
        for (int i = 0; i < TN; i++) {
            unsigned int lo, hi;
            asm("mov.b64 {%0, %1}, %2;" : "=r"(lo), "=r"(hi) : "l"(acc[p][i]));
            int col = tx + i * TNG;
            if (r < NV)     g_raw[(size_t)r * COUT + col]       = __uint_as_float(lo);
            if (r + 1 < NV) g_raw[(size_t)(r + 1) * COUT + col] = __uint_as_float(hi);
        }
    }
}

// ---------------- BatchNorm statistics ----------------
template <int COUT>
__global__ void k_stats1() {
    constexpr int RP = 256 / COUT;
    int tid = threadIdx.x;
    int col = tid % COUT, rg = tid / COUT;
    float s = 0.f, q = 0.f;
    for (int r = blockIdx.x * RP + rg; r < NV; r += NPART * RP) {
        float v = g_raw[(size_t)r * COUT + col];
        s += v;
        q += v * v;
    }
    __shared__ float sh[256], sh2[256];
    sh[tid] = s; sh2[tid] = q;
    __syncthreads();
    if (rg == 0) {
#pragma unroll
        for (int g2 = 1; g2 < RP; g2++) { s += sh[g2 * COUT + col]; q += sh2[g2 * COUT + col]; }
        g_part[blockIdx.x * 2 * COUT + col]        = s;
        g_part[blockIdx.x * 2 * COUT + COUT + col] = q;
    }
}

template <int COUT>
__global__ void k_stats2() {
    int col = threadIdx.x;
    if (col >= COUT) return;
    double s = 0.0, q = 0.0;
    for (int b = 0; b < NPART; b++) {
        s += (double)g_part[b * 2 * COUT + col];
        q += (double)g_part[b * 2 * COUT + COUT + col];
    }
    double mu  = s / (double)NV;
    double var = q / (double)NV - mu * mu;
    g_mu[col]   = (float)mu;
    g_istd[col] = (float)(1.0 / sqrt(var + 1e-3));
}

// ---------------- host orchestration ----------------
template <int CIN, int COUT>
static void run_tensor_block(const float* wb, const float* ws) {
    k_wc3<CIN, COUT><<<(27 * 4 * CIN * COUT + 255) / 256, 256>>>(wb, ws);
    dim3 grid((NV + 127) / 128, COUT / 64);
    k_hgemm<CIN, COUT><<<grid, 256>>>();
    k_stats1<COUT><<<NPART, 256>>>();
    k_stats2<COUT><<<1, 128>>>();
}

extern "C" void kernel_launch(void* const* d_in, const int* in_sizes, int n_in,
                              void* d_out, int out_size) {
    const float* vf    = (const float*)d_in[0];
    const int*   coors = (const int*)d_in[1];
    const float *wb[5], *ws[5], *gm[5], *bt[5];
    for (int i = 0; i < 5; i++) {
        wb[i] = (const float*)d_in[3 + 4 * i];
        ws[i] = (const float*)d_in[4 + 4 * i];
        gm[i] = (const float*)d_in[5 + 4 * i];
        bt[i] = (const float*)d_in[6 + 4 * i];
    }

    // rulebook + layer-1 phi
    k_initgrid<<<(2 * GD * GH * GW + 255) / 256, 256>>>();
    k_scatgrid<<<(NV + 255) / 256, 256>>>(coors);
    k_nbr<<<(NV + 255) / 256, 256>>>(coors);
    k_phi_in<<<(((NV + 1) * 16) + 255) / 256, 256>>>(vf);

    // L1: 16 -> 16 (f32x2)
    k_wc<16, 16><<<(27 * 64 * 16 + 255) / 256, 256>>>(wb[0], ws[0]);
    k_gemm<16, 16, 8, 2><<<(NV + 255) / 256, 256>>>();
    k_stats1<16><<<NPART, 256>>>();
    k_stats2<16><<<1, 128>>>();
    k_bnphi<16><<<(int)((((long)(NV + 1) * 16) + 255) / 256), 256>>>(gm[0], bt[0]);

    // L2: 16 -> 32 (f32x2), output split to bf16 hi/lo for L3
    k_wc<16, 32><<<(27 * 64 * 32 + 255) / 256, 256>>>(wb[1], ws[1]);
    k_gemm<16, 32, 8, 4><<<(NV + 255) / 256, 256>>>();
    k_stats1<32><<<NPART, 256>>>();
    k_stats2<32><<<1, 128>>>();
    k_bnphib<32><<<(int)((((long)(NV + 1) * 32) + 255) / 256), 256>>>(gm[1], bt[1]);

    // L3: 32 -> 64 (bf16 mma)
    run_tensor_block<32, 64>(wb[2], ws[2]);
    k_bnphib<64><<<(int)((((long)(NV + 1) * 64) + 255) / 256), 256>>>(gm[2], bt[2]);

    // L4: 64 -> 64 (bf16 mma)
    run_tensor_block<64, 64>(wb[3], ws[3]);
    k_bnphib<64><<<(int)((((long)(NV + 1) * 64) + 255) / 256), 256>>>(gm[3], bt[3]);

    // L5: 64 -> 128 (bf16 mma, two 64-col halves)
    run_tensor_block<64, 128>(wb[4], ws[4]);

    // zero dense output (poisoned by harness), then fused BN+ReLU+scatter
    long n4 = (long)out_size / 4;
    k_zero4<<<(int)((n4 + 255) / 256), 256>>>((float4*)d_out, n4);
    k_bnscat<<<(int)((((long)NV * 128) + 255) / 256), 256>>>(coors, gm[4], bt[4], (float*)d_out);
}

// round 17
// speedup vs baseline: 1.7998x; 1.0003x over previous
#include <cuda_runtime.h>
#include <cuda_bf16.h>

#define NV 50000
#define GD 10
#define GH 162
#define GW 162
#define NPART 240

// ---------------- device scratch (no allocations allowed) ----------------
__device__ int    g_grid[2 * GD * GH * GW];
__device__ int    g_nbr[27 * NV];
__device__ float4 g_phi[(NV + 1) * 16];                                 // f32 phi (CIN=16 layers)
__device__ __align__(16) unsigned short g_phh[(size_t)(NV + 1) * 256];  // bf16 hi phi
__device__ __align__(16) unsigned short g_phl[(size_t)(NV + 1) * 256];  // bf16 lo phi
__device__ __align__(16) unsigned short g_w3h[27 * 8 * 2 * 2560];       // W^T hi tiles [o][k] pad40
__device__ __align__(16) unsigned short g_w3l[27 * 8 * 2 * 2560];       // W^T lo tiles
__device__ __align__(16) float g_wc[27 * 64 * 32];                      // f32 W (L1/L2)
__device__ __align__(16) float g_raw[NV * 128];
__device__ float g_part[NPART * 2 * 128];
__device__ float g_mu[128];
__device__ float g_istd[128];

// ---------------- helpers ----------------
__device__ __forceinline__ unsigned smem_u32(const void* p) {
    unsigned a;
    asm("{ .reg .u64 t; cvta.to.shared.u64 t, %1; cvt.u32.u64 %0, t; }" : "=r"(a) : "l"(p));
    return a;
}
#define LDSM4(rg, addr)                                                              \
    asm volatile("ldmatrix.sync.aligned.m8n8.x4.shared.b16 {%0,%1,%2,%3}, [%4];"     \
        : "=r"((rg)[0]), "=r"((rg)[1]), "=r"((rg)[2]), "=r"((rg)[3]) : "r"(addr))
#define MMA_BF16(d, a, b0, b1)                                                       \
    asm volatile("mma.sync.aligned.m16n8k16.row.col.f32.bf16.bf16.f32 "              \
        "{%0,%1,%2,%3}, {%4,%5,%6,%7}, {%8,%9}, {%0,%1,%2,%3};"                      \
        : "+f"((d)[0]), "+f"((d)[1]), "+f"((d)[2]), "+f"((d)[3])                     \
        : "r"((a)[0]), "r"((a)[1]), "r"((a)[2]), "r"((a)[3]), "r"(b0), "r"(b1))

// ---------------- small utility kernels ----------------
__global__ void k_zero4(float4* p, long n4) {
    long i = (long)blockIdx.x * blockDim.x + threadIdx.x;
    if (i < n4) p[i] = make_float4(0.f, 0.f, 0.f, 0.f);
}

__global__ void k_initgrid() {
    int i = blockIdx.x * blockDim.x + threadIdx.x;
    if (i < 2 * GD * GH * GW) g_grid[i] = NV;
}

__global__ void k_scatgrid(const int* __restrict__ coors) {
    int n = blockIdx.x * blockDim.x + threadIdx.x;
    if (n >= NV) return;
    int b = coors[4 * n], z = coors[4 * n + 1], y = coors[4 * n + 2], x = coors[4 * n + 3];
    g_grid[((b * GD + z + 1) * GH + y + 1) * GW + x + 1] = n;
}

__global__ void k_nbr(const int* __restrict__ coors) {
    int n = blockIdx.x * blockDim.x + threadIdx.x;
    if (n >= NV) return;
    int b = coors[4 * n], z = coors[4 * n + 1] + 1, y = coors[4 * n + 2] + 1, x = coors[4 * n + 3] + 1;
    int k = 0;
#pragma unroll
    for (int dz = -1; dz <= 1; dz++)
#pragma unroll
        for (int dy = -1; dy <= 1; dy++)
#pragma unroll
            for (int dx = -1; dx <= 1; dx++) {
                g_nbr[k * NV + n] = g_grid[((b * GD + z + dz) * GH + y + dy) * GW + x + dx];
                k++;
            }
}

__device__ __forceinline__ float4 phi_of(float x) {
    float s  = x / (1.f + expf(-x));
    float b0 = expf(-(x + 1.f) * (x + 1.f));
    float b1 = expf(-x * x);
    float b2 = expf(-(x - 1.f) * (x - 1.f));
    return make_float4(s, b0, b1, b2);
}

__global__ void k_phi_in(const float* __restrict__ ext) {
    int t = blockIdx.x * blockDim.x + threadIdx.x;
    if (t >= (NV + 1) * 16) return;
    float x = (t < NV * 16) ? ext[t] : 0.f;
    g_phi[t] = phi_of(x);
}

// BN + ReLU + f32 phi (feeds L2's f32x2 GEMM)
template <int COUT>
__global__ void k_bnphi(const float* __restrict__ gm, const float* __restrict__ bt) {
    long t = (long)blockIdx.x * 256 + threadIdx.x;
    if (t >= (long)(NV + 1) * COUT) return;
    float x = 0.f;
    if (t < (long)NV * COUT) {
        int col = (int)(t % COUT);
        float v = (g_raw[t] - g_mu[col]) * g_istd[col] * gm[col] + bt[col];
        x = fmaxf(v, 0.f);
    }
    g_phi[t] = phi_of(x);
}

// BN + ReLU + bf16 hi/lo phi split (feeds tensor layers)
template <int COUT>
__global__ void k_bnphib(const float* __restrict__ gm, const float* __restrict__ bt) {
    long t = (long)blockIdx.x * 256 + threadIdx.x;
    if (t >= (long)(NV + 1) * COUT) return;
    float x = 0.f;
    if (t < (long)NV * COUT) {
        int col = (int)(t % COUT);
        float v = (g_raw[t] - g_mu[col]) * g_istd[col] * gm[col] + bt[col];
        x = fmaxf(v, 0.f);
    }
    float4 p = phi_of(x);
    float vals[4] = {p.x, p.y, p.z, p.w};
    size_t b = (size_t)t * 4;
#pragma unroll
    for (int i = 0; i < 4; i++) {
        __nv_bfloat16 h = __float2bfloat16_rn(vals[i]);
        __nv_bfloat16 l = __float2bfloat16_rn(vals[i] - __bfloat162float(h));
        g_phh[b + i] = __bfloat16_as_ushort(h);
        g_phl[b + i] = __bfloat16_as_ushort(l);
    }
}

__global__ void k_bnscat(const int* __restrict__ coors,
                         const float* __restrict__ gm, const float* __restrict__ bt,
                         float* __restrict__ out) {
    long t = (long)blockIdx.x * 256 + threadIdx.x;
    if (t >= (long)NV * 128) return;
    int n = (int)(t >> 7);
    int c = (int)(t & 127);
    float v = (g_raw[t] - g_mu[c]) * g_istd[c] * gm[c] + bt[c];
    v = fmaxf(v, 0.f);
    int b = coors[4 * n], z = coors[4 * n + 1], y = coors[4 * n + 2], x = coors[4 * n + 3];
    long oi = (((long)(b * 1024 + c * 8 + z)) * 160 + y) * 160 + x;
    out[oi] = v;
}

// combined f32 weights for L1/L2
template <int CIN, int COUT>
__global__ void k_wc(const float* __restrict__ wb, const float* __restrict__ ws) {
    int t = blockIdx.x * blockDim.x + threadIdx.x;
    if (t >= 27 * 4 * CIN * COUT) return;
    int o = t % COUT;
    int r = t / COUT;
    int j = r % (4 * CIN);
    int k = r / (4 * CIN);
    int c = j >> 2, jj = j & 3;
    g_wc[t] = (jj == 0) ? wb[(k * CIN + c) * COUT + o]
                        : ws[((k * CIN + c) * 3 + (jj - 1)) * COUT + o];
}

// W^T bf16 hi/lo tiles for tensor layers: tile(k, chunk, half) = [64 o-rows][32 k-cols pad 40]
template <int CIN, int COUT>
__global__ void k_wc3(const float* __restrict__ wb, const float* __restrict__ ws) {
    constexpr int KD = 4 * CIN, CPT = KD / 32, NH = COUT / 64;
    int t = blockIdx.x * blockDim.x + threadIdx.x;
    if (t >= 27 * KD * COUT) return;
    int o = t % COUT;
    int j = (t / COUT) % KD;
    int k = t / (COUT * KD);
    int c = j >> 2, jj = j & 3;
    float w = (jj == 0) ? wb[(k * CIN + c) * COUT + o]
                        : ws[((k * CIN + c) * 3 + (jj - 1)) * COUT + o];
    __nv_bfloat16 h = __float2bfloat16_rn(w);
    __nv_bfloat16 l = __float2bfloat16_rn(w - __bfloat162float(h));
    int tile = (k * CPT + (j >> 5)) * NH + (o >> 6);
    size_t dst = (size_t)tile * 2560 + (size_t)(o & 63) * 40 + (j & 31);
    g_w3h[dst] = __bfloat16_as_ushort(h);
    g_w3l[dst] = __bfloat16_as_ushort(l);
}

// ---------------- mma.sync bf16 gather-GEMM, 2-stage double buffer ----------------
// CTA: 128 voxels x 64 cols (half hy), 8 warps in 4(M) x 2(N); warp tile 32x32.
// Stage s = cid&1; per chunk: LDG c+1 -> compute(c, stage s) -> store c+1 into
// stage s^1 -> ONE barrier. Gather latency overlaps MMA issue; the stage being
// written is never the stage being read (previous read drained at last barrier).
template <int CIN, int COUT>
__global__ __launch_bounds__(256) void k_hgemm() {
    constexpr int KD = 4 * CIN, CPT = KD / 32, NH = COUT / 64, NCH = 27 * CPT;
    constexpr int SA = 128 * 40, SW = 64 * 40;          // elements per array
    constexpr int STG = 2 * SA + 2 * SW;                // elements per stage (15360)
    extern __shared__ __align__(16) unsigned short sbuf[];   // 2 stages = 61440 B

    int tid  = threadIdx.x, lane = tid & 31, wid = tid >> 5;
    int wm   = wid & 3, wn = wid >> 2;
    int m0   = blockIdx.x * 128;
    int hy   = blockIdx.y;
    int nofs = hy * 64;
    int r    = tid >> 1, half = tid & 1;
    int am   = m0 + r;
    unsigned sb = smem_u32(sbuf);

    float acc[2][4][4];
#pragma unroll
    for (int mt = 0; mt < 2; mt++)
#pragma unroll
        for (int nf = 0; nf < 4; nf++)
#pragma unroll
            for (int e = 0; e < 4; e++) acc[mt][nf][e] = 0.f;

    // ldmatrix stage-0 base addresses (add s*STG*2 bytes for stage s)
    unsigned ah_base[2], al_base[2], bh_base[2], bl_base[2];
#pragma unroll
    for (int mt = 0; mt < 2; mt++) {
        int rowA = wm * 32 + mt * 16 + (lane & 15);
        unsigned co = (unsigned)(8 * (lane >> 4));
        ah_base[mt] = sb + (unsigned)(rowA * 40 + co) * 2;
        al_base[mt] = sb + (unsigned)(SA + rowA * 40 + co) * 2;
    }
#pragma unroll
    for (int nt = 0; nt < 2; nt++) {
        int rowB = wn * 32 + nt * 16 + (lane & 7) + ((lane >> 4) << 3);
        unsigned co = (unsigned)(((lane >> 3) & 1) * 8);
        bh_base[nt] = sb + (unsigned)(2 * SA + rowB * 40 + co) * 2;
        bl_base[nt] = sb + (unsigned)(2 * SA + SW + rowB * 40 + co) * 2;
    }
    unsigned aoff = (unsigned)(r * 40 + half * 16) * 2;   // A store offset (bytes)

    uint4 h0, h1, l0, l1, wh0, wl0, wh1, wl1;

    auto loadregs = [&](int cid) {
        int tap = cid / CPT, q = cid % CPT;
        int idx = (am < NV) ? __ldg(&g_nbr[tap * NV + am]) : NV;   // NV -> phi(0) pad row
        const uint4* ph = (const uint4*)(g_phh + (size_t)idx * KD + q * 32 + half * 16);
        const uint4* pl = (const uint4*)(g_phl + (size_t)idx * KD + q * 32 + half * 16);
        h0 = ph[0]; h1 = ph[1]; l0 = pl[0]; l1 = pl[1];
        int tile = cid * NH + hy;
        const uint4* wph = (const uint4*)(g_w3h + (size_t)tile * 2560);
        const uint4* wpl = (const uint4*)(g_w3l + (size_t)tile * 2560);
        wh0 = wph[tid]; wl0 = wpl[tid];
        if (tid < 64) { wh1 = wph[tid + 256]; wl1 = wpl[tid + 256]; }
    };
    auto storestage = [&](int s) {
        unsigned b = sb + (unsigned)(s * STG) * 2;
        unsigned a0 = b + aoff;
        asm volatile("st.shared.v4.b32 [%0], {%1,%2,%3,%4};"
                     :: "r"(a0), "r"(h0.x), "r"(h0.y), "r"(h0.z), "r"(h0.w) : "memory");
        asm volatile("st.shared.v4.b32 [%0], {%1,%2,%3,%4};"
                     :: "r"(a0 + 16), "r"(h1.x), "r"(h1.y), "r"(h1.z), "r"(h1.w) : "memory");
        unsigned a1 = b + (unsigned)SA * 2 + aoff;
        asm volatile("st.shared.v4.b32 [%0], {%1,%2,%3,%4};"
                     :: "r"(a1), "r"(l0.x), "r"(l0.y), "r"(l0.z), "r"(l0.w) : "memory");
        asm volatile("st.shared.v4.b32 [%0], {%1,%2,%3,%4};"
                     :: "r"(a1 + 16), "r"(l1.x), "r"(l1.y), "r"(l1.z), "r"(l1.w) : "memory");
        uint4* whp = (uint4*)(sbuf + s * STG + 2 * SA);
        uint4* wlp = (uint4*)(sbuf + s * STG + 2 * SA + SW);
        whp[tid] = wh0;
        wlp[tid] = wl0;
        if (tid < 64) { whp[tid + 256] = wh1; wlp[tid + 256] = wl1; }
    };

    // prologue: stage chunk 0
    loadregs(0);
    storestage(0);
    __syncthreads();

    for (int cid = 0; cid < NCH; cid++) {
        int s = cid & 1;
        if (cid + 1 < NCH) loadregs(cid + 1);   // LDGs overlap this chunk's MMAs

        unsigned soff = (unsigned)(s * STG) * 2;
#pragma unroll
        for (int ks = 0; ks < 2; ks++) {
            unsigned ko = soff + (unsigned)(ks * 32);
            unsigned ah[2][4], al[2][4], bh[2][4], bl[2][4];
#pragma unroll
            for (int mt = 0; mt < 2; mt++) {
                LDSM4(ah[mt], ah_base[mt] + ko);
                LDSM4(al[mt], al_base[mt] + ko);
            }
#pragma unroll
            for (int nt = 0; nt < 2; nt++) {
                LDSM4(bh[nt], bh_base[nt] + ko);
                LDSM4(bl[nt], bl_base[nt] + ko);
            }
#pragma unroll
            for (int mt = 0; mt < 2; mt++)
#pragma unroll
                for (int nf = 0; nf < 4; nf++) {
                    unsigned bh0 = bh[nf >> 1][2 * (nf & 1)];
                    unsigned bh1 = bh[nf >> 1][2 * (nf & 1) + 1];
                    unsigned bl0 = bl[nf >> 1][2 * (nf & 1)];
                    unsigned bl1 = bl[nf >> 1][2 * (nf & 1) + 1];
                    MMA_BF16(acc[mt][nf], ah[mt], bh0, bh1);
                    MMA_BF16(acc[mt][nf], al[mt], bh0, bh1);
                    MMA_BF16(acc[mt][nf], ah[mt], bl0, bl1);
                }
        }

        if (cid + 1 < NCH) storestage(s ^ 1);   // write the buffer NOT being read
        __syncthreads();
    }

    // epilogue: acc layout rows l/4 (+8), cols 2*(l%4) (+1)
#pragma unroll
    for (int mt = 0; mt < 2; mt++) {
#pragma unroll
        for (int nf = 0; nf < 4; nf++) {
            int rr = m0 + wm * 32 + mt * 16 + (lane >> 2);
            int cc = nofs + wn * 32 + nf * 8 + 2 * (lane & 3);
            if (rr < NV) {
                g_raw[(size_t)rr * COUT + cc]     = acc[mt][nf][0];
                g_raw[(size_t)rr * COUT + cc + 1] = acc[mt][nf][1];
            }
            if (rr + 8 < NV) {
                g_raw[(size_t)(rr + 8) * COUT + cc]     = acc[mt][nf][2];
                g_raw[(size_t)(rr + 8) * COUT + cc + 1] = acc[mt][nf][3];
            }
        }
    }
}

// ---------------- f32x2 gather-GEMM (L1/L2, proven) ----------------
__device__ __forceinline__ unsigned long long ffma2(unsigned long long a,
                                                    unsigned long long b,
                                                    unsigned long long c) {
    unsigned long long d;
    asm("fma.rn.f32x2 %0, %1, %2, %3;" : "=l"(d) : "l"(a), "l"(b), "l"(c));
    return d;
}

template <int CIN, int COUT, int RT, int TN>
__global__ __launch_bounds__(256) void k_gemm() {
    constexpr int KD  = 4 * CIN;
    constexpr int KC  = 32;
    constexpr int CPT = KD / KC;
    constexpr int NCH = 27 * CPT;
    constexpr int TM  = 256;
    constexpr int TNG = COUT / TN;
    constexpr int P   = RT / 2;
    constexpr int WF2 = KC * COUT / 512;
    static_assert((256 / TNG) * RT == TM && P % 2 == 0 && WF2 >= 1, "tiling");

    __shared__ __align__(16) float As[KC][TM];
    __shared__ __align__(16) float Ws[KC][COUT];

    int tid  = threadIdx.x;
    int tx   = tid % TNG;
    int ty   = tid / TNG;
    int row0 = ty * RT;
    int m0   = blockIdx.x * TM;
    int am   = m0 + tid;
    bool avalid = (am < NV);

    unsigned long long acc[P][TN];
#pragma unroll
    for (int p = 0; p < P; p++)
#pragma unroll
        for (int i = 0; i < TN; i++) acc[p][i] = 0ull;

    int idx = NV;
    for (int cid = 0; cid < NCH; cid++) {
        int tap = cid / CPT;
        int jc  = (cid % CPT) * KC;
        if (cid % CPT == 0)
            idx = avalid ? __ldg(&g_nbr[tap * NV + am]) : NV;
        float4 areg[8];
        const float4* prow = g_phi + (size_t)idx * CIN + (jc >> 2);
#pragma unroll
        for (int q = 0; q < 8; q++) areg[q] = prow[q];
        float2 wreg[WF2];
        const float2* wbase = (const float2*)(g_wc + ((size_t)tap * KD + jc) * COUT);
#pragma unroll
        for (int v = 0; v < WF2; v++) wreg[v] = wbase[tid + v * 256];

        __syncthreads();
#pragma unroll
        for (int q = 0; q < 8; q++) {
            float4 v = areg[q];
            As[4 * q + 0][tid] = v.x;
            As[4 * q + 1][tid] = v.y;
            As[4 * q + 2][tid] = v.z;
            As[4 * q + 3][tid] = v.w;
        }
#pragma unroll
        for (int v = 0; v < WF2; v++) ((float2*)Ws)[tid + v * 256] = wreg[v];
        __syncthreads();

#pragma unroll
        for (int j = 0; j < KC; j++) {
            unsigned long long a[P];
            const ulonglong2* ap = (const ulonglong2*)&As[j][row0];
#pragma unroll
            for (int h = 0; h < P / 2; h++) {
                ulonglong2 t2 = ap[h];
                a[2 * h]     = t2.x;
                a[2 * h + 1] = t2.y;
            }
#pragma unroll
            for (int i = 0; i < TN; i++) {
                unsigned int bi = __float_as_uint(Ws[j][tx + i * TNG]);
                unsigned long long b2;
                asm("mov.b64 %0, {%1, %1};" : "=l"(b2) : "r"(bi));
#pragma unroll
                for (int p = 0; p < P; p++)
                    acc[p][i] = ffma2(a[p], b2, acc[p][i]);
            }
        }
    }

#pragma unroll
    for (int p = 0; p < P; p++) {
        int r = m0 + row0 + 2 * p;
#pragma unroll
        for (int i = 0; i < TN; i++) {
            unsigned int lo, hi;
            asm("mov.b64 {%0, %1}, %2;" : "=r"(lo), "=r"(hi) : "l"(acc[p][i]));
            int col = tx + i * TNG;
            if (r < NV)     g_raw[(size_t)r * COUT + col]       = __uint_as_float(lo);
            if (r + 1 < NV) g_raw[(size_t)(r + 1) * COUT + col] = __uint_as_float(hi);
        }
    }
}

// ---------------- BatchNorm statistics ----------------
template <int COUT>
__global__ void k_stats1() {
    constexpr int RP = 256 / COUT;
    int tid = threadIdx.x;
    int col = tid % COUT, rg = tid / COUT;
    float s = 0.f, q = 0.f;
    for (int r = blockIdx.x * RP + rg; r < NV; r += NPART * RP) {
        float v = g_raw[(size_t)r * COUT + col];
        s += v;
        q += v * v;
    }
    __shared__ float sh[256], sh2[256];
    sh[tid] = s; sh2[tid] = q;
    __syncthreads();
    if (rg == 0) {
#pragma unroll
        for (int g2 = 1; g2 < RP; g2++) { s += sh[g2 * COUT + col]; q += sh2[g2 * COUT + col]; }
        g_part[blockIdx.x * 2 * COUT + col]        = s;
        g_part[blockIdx.x * 2 * COUT + COUT + col] = q;
    }
}

template <int COUT>
__global__ void k_stats2() {
    int col = threadIdx.x;
    if (col >= COUT) return;
    double s = 0.0, q = 0.0;
    for (int b = 0; b < NPART; b++) {
        s += (double)g_part[b * 2 * COUT + col];
        q += (double)g_part[b * 2 * COUT + COUT + col];
    }
    double mu  = s / (double)NV;
    double var = q / (double)NV - mu * mu;
    g_mu[col]   = (float)mu;
    g_istd[col] = (float)(1.0 / sqrt(var + 1e-3));
}

// ---------------- host orchestration ----------------
template <int CIN, int COUT>
static void run_tensor_block(const float* wb, const float* ws) {
    k_wc3<CIN, COUT><<<(27 * 4 * CIN * COUT + 255) / 256, 256>>>(wb, ws);
    dim3 grid((NV + 127) / 128, COUT / 64);
    k_hgemm<CIN, COUT><<<grid, 256, 61440>>>();
    k_stats1<COUT><<<NPART, 256>>>();
    k_stats2<COUT><<<1, 128>>>();
}

extern "C" void kernel_launch(void* const* d_in, const int* in_sizes, int n_in,
                              void* d_out, int out_size) {
    const float* vf    = (const float*)d_in[0];
    const int*   coors = (const int*)d_in[1];
    const float *wb[5], *ws[5], *gm[5], *bt[5];
    for (int i = 0; i < 5; i++) {
        wb[i] = (const float*)d_in[3 + 4 * i];
        ws[i] = (const float*)d_in[4 + 4 * i];
        gm[i] = (const float*)d_in[5 + 4 * i];
        bt[i] = (const float*)d_in[6 + 4 * i];
    }

    // opt-in >48KB dynamic SMEM for the three hgemm instantiations (host attr, capture-safe)
    cudaFuncSetAttribute(k_hgemm<32, 64>,  cudaFuncAttributeMaxDynamicSharedMemorySize, 61440);
    cudaFuncSetAttribute(k_hgemm<64, 64>,  cudaFuncAttributeMaxDynamicSharedMemorySize, 61440);
    cudaFuncSetAttribute(k_hgemm<64, 128>, cudaFuncAttributeMaxDynamicSharedMemorySize, 61440);

    // rulebook + layer-1 phi
    k_initgrid<<<(2 * GD * GH * GW + 255) / 256, 256>>>();
    k_scatgrid<<<(NV + 255) / 256, 256>>>(coors);
    k_nbr<<<(NV + 255) / 256, 256>>>(coors);
    k_phi_in<<<(((NV + 1) * 16) + 255) / 256, 256>>>(vf);

    // L1: 16 -> 16 (f32x2)
    k_wc<16, 16><<<(27 * 64 * 16 + 255) / 256, 256>>>(wb[0], ws[0]);
    k_gemm<16, 16, 8, 2><<<(NV + 255) / 256, 256>>>();
    k_stats1<16><<<NPART, 256>>>();
    k_stats2<16><<<1, 128>>>();
    k_bnphi<16><<<(int)((((long)(NV + 1) * 16) + 255) / 256), 256>>>(gm[0], bt[0]);

    // L2: 16 -> 32 (f32x2), output split to bf16 hi/lo for L3
    k_wc<16, 32><<<(27 * 64 * 32 + 255) / 256, 256>>>(wb[1], ws[1]);
    k_gemm<16, 32, 8, 4><<<(NV + 255) / 256, 256>>>();
    k_stats1<32><<<NPART, 256>>>();
    k_stats2<32><<<1, 128>>>();
    k_bnphib<32><<<(int)((((long)(NV + 1) * 32) + 255) / 256), 256>>>(gm[1], bt[1]);

    // L3: 32 -> 64 (bf16 mma)
    run_tensor_block<32, 64>(wb[2], ws[2]);
    k_bnphib<64><<<(int)((((long)(NV + 1) * 64) + 255) / 256), 256>>>(gm[2], bt[2]);

    // L4: 64 -> 64 (bf16 mma)
    run_tensor_block<64, 64>(wb[3], ws[3]);
    k_bnphib<64><<<(int)((((long)(NV + 1) * 64) + 255) / 256), 256>>>(gm[3], bt[3]);

    // L5: 64 -> 128 (bf16 mma, two 64-col halves)
    run_tensor_block<64, 128>(wb[4], ws[4]);

    // zero dense output (poisoned by harness), then fused BN+ReLU+scatter
    long n4 = (long)out_size / 4;
    k_zero4<<<(int)((n4 + 255) / 256), 256>>>((float4*)d_out, n4);
    k_bnscat<<<(int)((((long)NV * 128) + 255) / 256), 256>>>(coors, gm[4], bt[4], (float*)d_out);
}